// round 17
// baseline (speedup 1.0000x reference)
#include <cuda_runtime.h>
#include <cstdint>

typedef unsigned int u32;

// Problem constants
#define N_TOK    16384
#define N_E      8192
#define E_DIM    256
#define OUT_ELEMS 4194304
#define LOSS_OFF  OUT_ELEMS
#define PERP_OFF  (OUT_ELEMS + 1)
#define IDX_OFF   (OUT_ELEMS + 2)
#define N_HALF   2
#define CAND_CAP 64

// Scratch (static device globals)
__device__ float g_wT[E_DIM * N_E];     // weight transposed [k][n] (gather)
__device__ float g_wn[N_E];             // |w_n|^2 (exact fp32)
__device__ float g_Azf[N_TOK * E_DIM];  // z rows fp32 [t][k] (rescore)
__device__ int   g_zq[64 * N_TOK];      // packed int8 z [kq][t]
__device__ int   g_wq[64 * N_E];        // packed int8 w [kq][n]
__device__ float g_l1z[N_TOK];          // L1 norm of z_t
__device__ int   g_amax_bits[2];        // amax(z), amax(w) as float bits
__device__ int   g_maxl1w_bits;         // max_n L1(w_n) as float bits
__device__ int   g_cand[N_TOK * CAND_CAP];
__device__ int   g_ccount[N_TOK];
__device__ int   g_idx[N_TOK];
__device__ int   g_counts[N_E];
__device__ float g_partial[256];

__device__ __forceinline__ u32 smem_u32(const void* p) {
    u32 a;
    asm("{ .reg .u64 t; cvta.to.shared.u64 t, %1; cvt.u32.u64 %0, t; }"
        : "=r"(a) : "l"(p));
    return a;
}
__device__ __forceinline__ void cp16(u32 dst, const void* src) {
    asm volatile("cp.async.cg.shared.global [%0], [%1], 16;"
                 :: "r"(dst), "l"(src));
}
__device__ __forceinline__ int dp4a(int a, int b, int c) {
    int d;
    asm("dp4a.s32.s32 %0, %1, %2, %3;" : "=r"(d) : "r"(a), "r"(b), "r"(c));
    return d;
}

// ---------------------------------------------------------------------------
__global__ void zero_kernel() {
    int i = blockIdx.x * 256 + threadIdx.x;
    if (i < N_E)   g_counts[i] = 0;
    if (i < N_TOK) { g_ccount[i] = 0; g_l1z[i] = 0.f; }
    if (i < 2)     g_amax_bits[i] = 0;
    if (i == 0)    g_maxl1w_bits = 0;
}

// ---------------------------------------------------------------------------
// abs-max reduction into g_amax_bits[slot] (positive float bits atomicMax)
__global__ void amax_kernel(const float* __restrict__ x, int n, int slot) {
    float m = 0.f;
    for (int i = blockIdx.x * blockDim.x + threadIdx.x; i < n;
         i += gridDim.x * blockDim.x)
        m = fmaxf(m, fabsf(x[i]));
#pragma unroll
    for (int off = 16; off >= 1; off >>= 1)
        m = fmaxf(m, __shfl_xor_sync(0xffffffffu, m, off));
    __shared__ float wm[8];
    int wid = threadIdx.x >> 5, lane = threadIdx.x & 31;
    if (lane == 0) wm[wid] = m;
    __syncthreads();
    if (threadIdx.x == 0) {
        float bm = wm[0];
#pragma unroll
        for (int i = 1; i < 8; i++) bm = fmaxf(bm, wm[i]);
        atomicMax(&g_amax_bits[slot], __float_as_int(bm));
    }
}

// ---------------------------------------------------------------------------
// Transpose weight [N_E, E_DIM] -> g_wT [E_DIM, N_E]
__global__ void transpose_kernel(const float* __restrict__ w) {
    __shared__ float tile[32][33];
    int bx = blockIdx.x, by = blockIdx.y;
    int tx = threadIdx.x, ty = threadIdx.y;
#pragma unroll
    for (int j = 0; j < 32; j += 8)
        tile[ty + j][tx] = w[(by * 32 + ty + j) * E_DIM + bx * 32 + tx];
    __syncthreads();
#pragma unroll
    for (int j = 0; j < 32; j += 8)
        g_wT[(bx * 32 + ty + j) * N_E + by * 32 + tx] = tile[tx][ty + j];
}

// ---------------------------------------------------------------------------
__global__ void wn_kernel() {
    int j = blockIdx.x * 256 + threadIdx.x;
    float s = 0.f;
#pragma unroll 8
    for (int k = 0; k < E_DIM; k++) {
        float v = g_wT[k * N_E + j];
        s = fmaf(v, v, s);
    }
    g_wn[j] = s;
}

// ---------------------------------------------------------------------------
// Quantize w (from g_wT, coalesced) -> g_wq [kq][n]; track max L1(w_n).
__global__ void wquant_kernel() {
    int n = blockIdx.x * 256 + threadIdx.x;
    float sw = 127.f / fmaxf(__int_as_float(g_amax_bits[1]), 1e-20f);
    float l1 = 0.f;
#pragma unroll 4
    for (int kq = 0; kq < 64; kq++) {
        int pk = 0;
#pragma unroll
        for (int c = 0; c < 4; c++) {
            float v = g_wT[(kq * 4 + c) * N_E + n];
            l1 += fabsf(v);
            int q = __float2int_rn(v * sw);
            q = max(-127, min(127, q));
            pk |= (q & 0xff) << (c * 8);
        }
        g_wq[kq * N_E + n] = pk;
    }
    atomicMax(&g_maxl1w_bits, __float_as_int(l1));
}

// ---------------------------------------------------------------------------
// z [b,c,s] -> g_Azf [t][k] fp32  +  g_zq packed int8 [kq][t]  +  l1z partials
__global__ void zprep_kernel(const float* __restrict__ z) {
    __shared__ float tile[32][33];
    int k0 = blockIdx.x * 32, s0 = blockIdx.y * 32, b = blockIdx.z;
    int tx = threadIdx.x, ty = threadIdx.y;
#pragma unroll
    for (int j = 0; j < 32; j += 8)
        tile[ty + j][tx] = z[(size_t)b * 1048576 + (size_t)(k0 + ty + j) * 4096 + s0 + tx];
    __syncthreads();
    // fp32 token rows (coalesced along k)
#pragma unroll
    for (int j = 0; j < 32; j += 8) {
        int t = b * 4096 + s0 + ty + j;
        g_Azf[(size_t)t * 256 + k0 + tx] = tile[tx][ty + j];
    }
    // int8 pack: thread (tx=token, ty=kq-row)
    {
        float sz = 127.f / fmaxf(__int_as_float(g_amax_bits[0]), 1e-20f);
        int t = b * 4096 + s0 + tx;
        int pk = 0;
        float l1 = 0.f;
#pragma unroll
        for (int c = 0; c < 4; c++) {
            float v = tile[ty * 4 + c][tx];
            l1 += fabsf(v);
            int q = __float2int_rn(v * sz);
            q = max(-127, min(127, q));
            pk |= (q & 0xff) << (c * 8);
        }
        g_zq[(blockIdx.x * 8 + ty) * N_TOK + t] = pk;
        atomicAdd(&g_l1z[t], l1);
    }
}

// ---------------------------------------------------------------------------
// Coarse int8 dp4a GEMM + rigorous-margin candidate collection.
// grid (128, 2): 128 tokens x half the codebook per CTA.
#define BKq 16                  // int32 rows per tile = 64 dims
#define TZQ (BKq * 128)
#define TWQ (BKq * 128)
#define CSMEM_BYTES (2 * (TZQ + TWQ) * 4 + 512)

__global__ __launch_bounds__(256, 2) void coarse_kernel() {
    extern __shared__ int smem_i[];
    int*   zqs  = smem_i;                      // [2][16][128]
    int*   wqs  = smem_i + 2 * TZQ;            // [2][16][128]
    float* rmin = (float*)(smem_i + 2 * TZQ + 2 * TWQ);  // [128]

    const int tid = threadIdx.x;
    const int tx = tid & 15, ty = tid >> 4;
    const int t0 = blockIdx.x * 128;
    const int half = blockIdx.y;
    const int nt_beg = half * (N_E / N_HALF / 128);   // 32 n-tiles per half

    if (tid < 128) rmin[tid] = 3.4e38f;

    const float sz = 127.f / fmaxf(__int_as_float(g_amax_bits[0]), 1e-20f);
    const float sw = 127.f / fmaxf(__int_as_float(g_amax_bits[1]), 1e-20f);
    const float n2inv = -2.f / (sz * sw);
    const float maxl1w = __int_as_float(g_maxl1w_bits);
    const float cz = 0.5f / sz, cw = 0.5f / sw;
    float marg[8];
#pragma unroll
    for (int i = 0; i < 8; i++) {
        float l1 = g_l1z[t0 + ty * 8 + i];
        marg[i] = 2.f * (cz * maxl1w + cw * (l1 + 256.f * cz)) + 1.0f;
    }

    const u32 zqs_s = smem_u32(zqs);
    const u32 wqs_s = smem_u32(wqs);
    const int S = (N_E / N_HALF / 128) * 4;   // 128 stages (4 k-tiles per n-tile)

    auto stage = [&](int s) {
        const int kt = s & 3, nt = nt_beg + (s >> 2);
        const int kq0 = kt * BKq, n0 = nt * 128;
        const int buf = s & 1;
        const u32 zdst = zqs_s + (u32)(buf * TZQ * 4);
        const u32 wdst = wqs_s + (u32)(buf * TWQ * 4);
#pragma unroll
        for (int it = 0; it < 2; it++) {
            int slot = it * 256 + tid;
            int r = slot >> 5, c4 = (slot & 31) << 2;
            cp16(zdst + (u32)((r * 128 + c4) * 4),
                 &g_zq[(kq0 + r) * N_TOK + t0 + c4]);
        }
#pragma unroll
        for (int it = 0; it < 2; it++) {
            int slot = it * 256 + tid;
            int r = slot >> 5, c4 = (slot & 31) << 2;
            cp16(wdst + (u32)((r * 128 + c4) * 4),
                 &g_wq[(kq0 + r) * N_E + n0 + c4]);
        }
        asm volatile("cp.async.commit_group;" ::: "memory");
    };

    int acc[8][8];
#pragma unroll
    for (int i = 0; i < 8; i++)
#pragma unroll
        for (int j = 0; j < 8; j++) acc[i][j] = 0;

    stage(0);

    for (int s = 0; s < S; s++) {
        const int buf = s & 1;
        const int kt = s & 3;
        const int n0 = (nt_beg + (s >> 2)) * 128;

        if (s + 1 < S) {
            stage(s + 1);
            asm volatile("cp.async.wait_group 1;" ::: "memory");
        } else {
            asm volatile("cp.async.wait_group 0;" ::: "memory");
        }
        __syncthreads();

        const int* zb_ = zqs + buf * TZQ;
        const int* wb_ = wqs + buf * TWQ;
#pragma unroll
        for (int kq = 0; kq < BKq; kq++) {
            int4 za = *(const int4*)&zb_[kq * 128 + ty * 8];
            int4 zc = *(const int4*)&zb_[kq * 128 + ty * 8 + 4];
            int4 wa = *(const int4*)&wb_[kq * 128 + tx * 8];
            int4 wc = *(const int4*)&wb_[kq * 128 + tx * 8 + 4];
            int zv[8] = {za.x, za.y, za.z, za.w, zc.x, zc.y, zc.z, zc.w};
            int wv[8] = {wa.x, wa.y, wa.z, wa.w, wc.x, wc.y, wc.z, wc.w};
#pragma unroll
            for (int i = 0; i < 8; i++)
#pragma unroll
                for (int j = 0; j < 8; j++)
                    acc[i][j] = dp4a(zv[i], wv[j], acc[i][j]);
        }
        __syncthreads();

        if (kt == 3) {
            float wn8[8];
#pragma unroll
            for (int j = 0; j < 8; j++) wn8[j] = g_wn[n0 + tx * 8 + j];

            float th[8];
#pragma unroll
            for (int i = 0; i < 8; i++) {
                float m = 3.4e38f;
#pragma unroll
                for (int j = 0; j < 8; j++) {
                    float sc = fmaf(n2inv, (float)acc[i][j], wn8[j]);
                    m = fminf(m, sc);
                }
#pragma unroll
                for (int off = 8; off >= 1; off >>= 1)
                    m = fminf(m, __shfl_xor_sync(0xffffffffu, m, off, 16));
                int tl = ty * 8 + i;
                float rm = fminf(rmin[tl], m);
                if (tx == 0) rmin[tl] = rm;
                th[i] = rm + marg[i];
            }
            // append pass (recompute scores; candidates are rare)
#pragma unroll
            for (int i = 0; i < 8; i++) {
                int t = t0 + ty * 8 + i;
#pragma unroll
                for (int j = 0; j < 8; j++) {
                    float sc = fmaf(n2inv, (float)acc[i][j], wn8[j]);
                    if (sc < th[i]) {
                        int pos = atomicAdd(&g_ccount[t], 1);
                        if (pos < CAND_CAP)
                            g_cand[(size_t)t * CAND_CAP + pos] = n0 + tx * 8 + j;
                    }
                    acc[i][j] = 0;
                }
            }
        }
    }
}

// ---------------------------------------------------------------------------
// Exact fp32 rescore (warp per token). True argmin guaranteed in candidate
// set by the quantization margin; overflow -> exact full scan.
__global__ __launch_bounds__(256) void rescore_kernel(const float* __restrict__ w) {
    const int wid = threadIdx.x >> 5, lane = threadIdx.x & 31;
    const int t = blockIdx.x * 8 + wid;

    const float4 za = *(const float4*)&g_Azf[(size_t)t * 256 + lane * 4];
    const float4 zb = *(const float4*)&g_Azf[(size_t)t * 256 + 128 + lane * 4];

    const int cntraw = g_ccount[t];
    const int ovf = cntraw > CAND_CAP;
    const int niter = ovf ? N_E : cntraw;

    float best = 3.4e38f;
    int   bi = 0x7fffffff;
    for (int it = 0; it < niter; it++) {
        const int j = ovf ? it : g_cand[(size_t)t * CAND_CAP + it];
        const float4 wa = *(const float4*)&w[(size_t)j * 256 + lane * 4];
        const float4 wb = *(const float4*)&w[(size_t)j * 256 + 128 + lane * 4];
        float d = za.x * wa.x;
        d = fmaf(za.y, wa.y, d);
        d = fmaf(za.z, wa.z, d);
        d = fmaf(za.w, wa.w, d);
        d = fmaf(zb.x, wb.x, d);
        d = fmaf(zb.y, wb.y, d);
        d = fmaf(zb.z, wb.z, d);
        d = fmaf(zb.w, wb.w, d);
#pragma unroll
        for (int off = 16; off >= 1; off >>= 1)
            d += __shfl_xor_sync(0xffffffffu, d, off);
        float score = fmaf(-2.f, d, g_wn[j]);
        if (score < best || (score == best && j < bi)) { best = score; bi = j; }
    }
    if (lane == 0) {
        g_idx[t] = bi;
        atomicAdd(&g_counts[bi], 1);
    }
}

// ---------------------------------------------------------------------------
// Gather + straight-through output + loss partials
__global__ __launch_bounds__(256) void gather_kernel(const float* __restrict__ z,
                                                     float* __restrict__ out,
                                                     int out_size) {
    __shared__ float red[256];
    const int blk = blockIdx.x;
    const int t0 = blk * 64;
    const int b  = t0 >> 12;
    const int s0 = t0 & 4095;
    const int tid = threadIdx.x;
    const int i  = tid & 63;
    const int cg = tid >> 6;
    const int t  = t0 + i;
    const int j  = g_idx[t];
    const size_t base = (size_t)b * 1048576 + s0 + i;

    float lsum = 0.f;
#pragma unroll 4
    for (int cc = 0; cc < 64; cc++) {
        int c = cg * 64 + cc;
        float zt = z[base + (size_t)c * 4096];
        float zq = g_wT[(size_t)c * N_E + j];
        float d = zq - zt;
        out[base + (size_t)c * 4096] = zt + d;
        lsum = fmaf(d, d, lsum);
    }

    red[tid] = lsum;
    __syncthreads();
    for (int s = 128; s >= 1; s >>= 1) {
        if (tid < s) red[tid] += red[tid + s];
        __syncthreads();
    }
    if (tid == 0) g_partial[blk] = red[0];

    if (cg == 0 && out_size >= IDX_OFF + N_TOK)
        out[IDX_OFF + t] = (float)j;
}

// ---------------------------------------------------------------------------
__global__ void final_kernel(float* __restrict__ out, int out_size) {
    __shared__ float red[256];
    const int tid = threadIdx.x;

    red[tid] = g_partial[tid];
    __syncthreads();
    for (int s = 128; s >= 1; s >>= 1) {
        if (tid < s) red[tid] += red[tid + s];
        __syncthreads();
    }
    float loss = 0.25f * red[0] / (float)OUT_ELEMS;
    __syncthreads();

    float h = 0.f;
#pragma unroll
    for (int k = 0; k < N_E / 256; k++) {
        float p = (float)g_counts[k * 256 + tid] * (1.f / (float)N_TOK);
        h += p * logf(p + 1e-10f);
    }
    red[tid] = h;
    __syncthreads();
    for (int s = 128; s >= 1; s >>= 1) {
        if (tid < s) red[tid] += red[tid + s];
        __syncthreads();
    }
    if (tid == 0) {
        if (out_size > LOSS_OFF) out[LOSS_OFF] = loss;
        if (out_size > PERP_OFF) out[PERP_OFF] = expf(-red[0]);
    }
}

// ---------------------------------------------------------------------------
extern "C" void kernel_launch(void* const* d_in, const int* in_sizes, int n_in,
                              void* d_out, int out_size) {
    const float* z = (const float*)d_in[0];
    const float* w = (const float*)d_in[1];
    if (n_in >= 2 && in_sizes[0] == N_E * E_DIM && in_sizes[1] == OUT_ELEMS) {
        const float* tmp = z; z = w; w = tmp;
    }
    float* out = (float*)d_out;

    zero_kernel<<<64, 256>>>();
    amax_kernel<<<256, 256>>>(z, OUT_ELEMS, 0);
    amax_kernel<<<64, 256>>>(w, N_E * E_DIM, 1);
    transpose_kernel<<<dim3(8, 256), dim3(32, 8)>>>(w);
    wn_kernel<<<N_E / 256, 256>>>();
    wquant_kernel<<<N_E / 256, 256>>>();
    zprep_kernel<<<dim3(8, 128, 4), dim3(32, 8)>>>(z);
    coarse_kernel<<<dim3(N_TOK / 128, N_HALF), 256, CSMEM_BYTES>>>();
    rescore_kernel<<<N_TOK / 8, 256>>>(w);
    gather_kernel<<<N_TOK / 64, 256>>>(z, out, out_size);
    final_kernel<<<1, 256>>>(out, out_size);
}